// round 2
// baseline (speedup 1.0000x reference)
#include <cuda_runtime.h>

#define NN 100000
#define EE 3200000
#define DD 192        // packed feature dim: 128 (x) + 64 (y)
#define L4 48         // float4 lanes per row (192/4)
#define ROWS_PER_BLK 4
#define HOPS 10

// ---- static scratch (no dynamic allocation allowed) ----
__device__ int    g_is64;          // 1 if edge_index is int64, 0 if int32
__device__ int    g_deg[NN];
__device__ int    g_cnt[NN];
__device__ int    g_fill[NN];
__device__ int    g_rowptr[NN + 1];
__device__ int    g_col[EE];
__device__ float  g_dinv[NN];
__device__ float4 g_v0[NN * L4];   // packed original features (unscaled)
__device__ float4 g_uA[NN * L4];   // u = dinv .* v  (ping)
__device__ float4 g_uB[NN * L4];   // (pong)

// ---------------- dtype detection ----------------
// int64 little-endian with values in [0, 2^31): every odd 32-bit word is 0.
// int32: odd words are random node ids (practically never all zero over 1024).
__global__ void k_detect(const int* __restrict__ w) {
    __shared__ int nz;
    if (threadIdx.x == 0) nz = 0;
    __syncthreads();
    int local = 0;
    for (int i = threadIdx.x; i < 1024; i += blockDim.x)
        if (w[2 * i + 1] != 0) local++;
    if (local) atomicAdd(&nz, local);
    __syncthreads();
    if (threadIdx.x == 0) g_is64 = (nz == 0) ? 1 : 0;
}

__device__ __forceinline__ int edge_val(const int* __restrict__ w, long long idx) {
    // idx in [0, 2*EE): logical element index into the edge_index array
    return g_is64 ? w[2 * idx] : w[idx];
}

// ---------------- CSR build ----------------

__global__ void k_init() {
    int i = blockIdx.x * blockDim.x + threadIdx.x;
    if (i < NN) { g_deg[i] = 1; g_cnt[i] = 0; g_fill[i] = 0; }
}

__global__ void k_hist(const int* __restrict__ w) {
    int e = blockIdx.x * blockDim.x + threadIdx.x;
    if (e < EE) {
        int s = edge_val(w, e);
        int d = edge_val(w, (long long)EE + e);
        if ((unsigned)s < NN && (unsigned)d < NN) {
            atomicAdd(&g_cnt[s], 1);   // CSR row sizes (by src)
            atomicAdd(&g_deg[d], 1);   // degree over dst (+1 self loop from init)
        }
    }
}

__global__ void k_dinv() {
    int i = blockIdx.x * blockDim.x + threadIdx.x;
    if (i < NN) g_dinv[i] = rsqrtf((float)g_deg[i]);
}

// single-block exclusive scan of g_cnt -> g_rowptr
__global__ void k_scan() {
    __shared__ int ssum[1024];
    const int T = 1024;
    int t = threadIdx.x;
    int per = (NN + T - 1) / T;
    int lo = t * per;
    int hi = lo + per; if (hi > NN) hi = NN;
    int s = 0;
    for (int i = lo; i < hi; i++) s += g_cnt[i];
    ssum[t] = s;
    __syncthreads();
    if (t == 0) {
        int acc = 0;
        for (int i = 0; i < T; i++) { int v = ssum[i]; ssum[i] = acc; acc += v; }
        g_rowptr[NN] = acc;
    }
    __syncthreads();
    int acc = ssum[t];
    for (int i = lo; i < hi; i++) { int v = g_cnt[i]; g_rowptr[i] = acc; acc += v; }
}

__global__ void k_scatter(const int* __restrict__ w) {
    int e = blockIdx.x * blockDim.x + threadIdx.x;
    if (e < EE) {
        int s = edge_val(w, e);
        int d = edge_val(w, (long long)EE + e);
        if ((unsigned)s < NN && (unsigned)d < NN) {
            int pos = g_rowptr[s] + atomicAdd(&g_fill[s], 1);
            g_col[pos] = d;
        }
    }
}

// pack x[N,128] + y[N,64] -> v0[N,192]; uA = dinv .* v0
__global__ void k_pack(const float* __restrict__ x, const float* __restrict__ y) {
    int i = blockIdx.x;          // row
    int d = threadIdx.x;         // 0..191
    float v = (d < 128) ? x[i * 128 + d] : y[i * 64 + (d - 128)];
    ((float*)g_v0)[i * DD + d] = v;
    ((float*)g_uA)[i * DD + d] = g_dinv[i] * v;
}

// ---------------- propagation hop ----------------
// (A_hat v)[i] = dinv[i] * ( u[i] + sum_{c in nbr(i)} u[c] ),  u = dinv .* v
// out = 0.9 * A_hat v + 0.1 * v0
// non-final: store u_out = dinv[i] * out ; final: unpack to d_out

template <bool FINAL>
__global__ void __launch_bounds__(ROWS_PER_BLK * L4)
k_hop(int parity, float* __restrict__ dout) {
    const float4* __restrict__ uin = parity ? g_uB : g_uA;
    float4* __restrict__ uout      = parity ? g_uA : g_uB;

    int tid  = threadIdx.x;
    int r    = blockIdx.x * ROWS_PER_BLK + tid / L4;
    int lane = tid % L4;
    if (r >= NN) return;

    int lo = g_rowptr[r];
    int hi = g_rowptr[r + 1];

    const float4* base = uin + lane;
    float4 acc = base[(size_t)r * L4];   // self loop contributes u[i]

    int e = lo;
    for (; e + 4 <= hi; e += 4) {
        int c0 = g_col[e], c1 = g_col[e + 1], c2 = g_col[e + 2], c3 = g_col[e + 3];
        float4 a = base[(size_t)c0 * L4];
        float4 b = base[(size_t)c1 * L4];
        float4 c = base[(size_t)c2 * L4];
        float4 d = base[(size_t)c3 * L4];
        acc.x += (a.x + b.x) + (c.x + d.x);
        acc.y += (a.y + b.y) + (c.y + d.y);
        acc.z += (a.z + b.z) + (c.z + d.z);
        acc.w += (a.w + b.w) + (c.w + d.w);
    }
    for (; e < hi; e++) {
        int c0 = g_col[e];
        float4 a = base[(size_t)c0 * L4];
        acc.x += a.x; acc.y += a.y; acc.z += a.z; acc.w += a.w;
    }

    float  di = g_dinv[r];
    float4 v0 = g_v0[(size_t)r * L4 + lane];
    float  s  = 0.9f * di;
    float4 o;
    o.x = s * acc.x + 0.1f * v0.x;
    o.y = s * acc.y + 0.1f * v0.y;
    o.z = s * acc.z + 0.1f * v0.z;
    o.w = s * acc.w + 0.1f * v0.w;

    if (FINAL) {
        // unpack: lanes 0..31 -> x region [N,128], lanes 32..47 -> y region [N,64]
        float4* o4 = (float4*)dout;
        if (lane < 32) o4[(size_t)r * 32 + lane] = o;
        else           o4[(size_t)NN * 32 + (size_t)r * 16 + (lane - 32)] = o;
    } else {
        uout[(size_t)r * L4 + lane] = make_float4(di * o.x, di * o.y, di * o.z, di * o.w);
    }
}

// ---------------- launch ----------------

extern "C" void kernel_launch(void* const* d_in, const int* in_sizes, int n_in,
                              void* d_out, int out_size) {
    const float* x  = (const float*)d_in[0];
    const float* y  = (const float*)d_in[1];
    const int*   ei = (const int*)d_in[2];   // raw 32-bit words; layout detected on-device
    float* out = (float*)d_out;

    const int TB = 256;
    k_detect<<<1, 256>>>(ei);
    k_init<<<(NN + TB - 1) / TB, TB>>>();
    k_hist<<<(EE + TB - 1) / TB, TB>>>(ei);
    k_dinv<<<(NN + TB - 1) / TB, TB>>>();
    k_scan<<<1, 1024>>>();
    k_scatter<<<(EE + TB - 1) / TB, TB>>>(ei);
    k_pack<<<NN, DD>>>(x, y);

    const int hopThreads = ROWS_PER_BLK * L4;                       // 192
    const int hopBlocks  = (NN + ROWS_PER_BLK - 1) / ROWS_PER_BLK;  // 25000
    for (int h = 0; h < HOPS - 1; h++)
        k_hop<false><<<hopBlocks, hopThreads>>>(h & 1, out);
    k_hop<true><<<hopBlocks, hopThreads>>>((HOPS - 1) & 1, out);
}

// round 3
// speedup vs baseline: 1.6387x; 1.6387x over previous
#include <cuda_runtime.h>
#include <cuda_fp16.h>

#define NN 100000
#define EE 3200000
#define DD 192        // packed feature dim: 128 (x) + 64 (y)
#define LH 24         // uint4 lanes per row (192 halves / 8 per 16B)
#define ROWS_PER_BLK 8
#define HOPS 10

// ---- static scratch (no dynamic allocation allowed) ----
__device__ int    g_is64;          // 1 if edge_index is int64, 0 if int32
__device__ int    g_deg[NN];
__device__ int    g_cnt[NN];
__device__ int    g_fill[NN];
__device__ int    g_rowptr[NN + 1];
__device__ int    g_col[EE];
__device__ float  g_dinv[NN];
__device__ uint4  g_v0h[NN * LH];  // 0.1 * v0, fp16 packed
__device__ uint4  g_uA[NN * LH];   // u = dinv .* v, fp16 (ping)
__device__ uint4  g_uB[NN * LH];   // (pong)

// ---------------- dtype detection ----------------
// int64 LE with values < 2^31: every odd 32-bit word is 0. int32: practically never.
__global__ void k_detect(const int* __restrict__ w) {
    __shared__ int nz;
    if (threadIdx.x == 0) nz = 0;
    __syncthreads();
    int local = 0;
    for (int i = threadIdx.x; i < 1024; i += blockDim.x)
        if (w[2 * i + 1] != 0) local++;
    if (local) atomicAdd(&nz, local);
    __syncthreads();
    if (threadIdx.x == 0) g_is64 = (nz == 0) ? 1 : 0;
}

__device__ __forceinline__ int edge_val(const int* __restrict__ w, long long idx) {
    return g_is64 ? w[2 * idx] : w[idx];
}

// ---------------- CSR build ----------------

__global__ void k_init() {
    int i = blockIdx.x * blockDim.x + threadIdx.x;
    if (i < NN) { g_deg[i] = 1; g_cnt[i] = 0; g_fill[i] = 0; }
}

__global__ void k_hist(const int* __restrict__ w) {
    int e = blockIdx.x * blockDim.x + threadIdx.x;
    if (e < EE) {
        int s = edge_val(w, e);
        int d = edge_val(w, (long long)EE + e);
        if ((unsigned)s < NN && (unsigned)d < NN) {
            atomicAdd(&g_cnt[s], 1);
            atomicAdd(&g_deg[d], 1);
        }
    }
}

__global__ void k_dinv() {
    int i = blockIdx.x * blockDim.x + threadIdx.x;
    if (i < NN) g_dinv[i] = rsqrtf((float)g_deg[i]);
}

__global__ void k_scan() {
    __shared__ int ssum[1024];
    const int T = 1024;
    int t = threadIdx.x;
    int per = (NN + T - 1) / T;
    int lo = t * per;
    int hi = lo + per; if (hi > NN) hi = NN;
    int s = 0;
    for (int i = lo; i < hi; i++) s += g_cnt[i];
    ssum[t] = s;
    __syncthreads();
    if (t == 0) {
        int acc = 0;
        for (int i = 0; i < T; i++) { int v = ssum[i]; ssum[i] = acc; acc += v; }
        g_rowptr[NN] = acc;
    }
    __syncthreads();
    int acc = ssum[t];
    for (int i = lo; i < hi; i++) { int v = g_cnt[i]; g_rowptr[i] = acc; acc += v; }
}

__global__ void k_scatter(const int* __restrict__ w) {
    int e = blockIdx.x * blockDim.x + threadIdx.x;
    if (e < EE) {
        int s = edge_val(w, e);
        int d = edge_val(w, (long long)EE + e);
        if ((unsigned)s < NN && (unsigned)d < NN) {
            int pos = g_rowptr[s] + atomicAdd(&g_fill[s], 1);
            g_col[pos] = d;
        }
    }
}

// pack x[N,128] + y[N,64] -> v0h = fp16(0.1*v), uA = fp16(dinv*v)
__global__ void k_pack(const float* __restrict__ x, const float* __restrict__ y) {
    int i = blockIdx.x;          // row
    int d = threadIdx.x;         // 0..191
    float v = (d < 128) ? x[i * 128 + d] : y[i * 64 + (d - 128)];
    ((__half*)g_v0h)[(size_t)i * DD + d] = __float2half(0.1f * v);
    ((__half*)g_uA)[(size_t)i * DD + d]  = __float2half(g_dinv[i] * v);
}

// ---------------- propagation hop ----------------
// (A_hat v)[i] = dinv[i] * ( u[i] + sum_{c in nbr(i)} u[c] ),  u = dinv .* v
// out = 0.9 * A_hat v + 0.1 * v0;  non-final stores fp16 u_out = dinv[i]*out

__device__ __forceinline__ void acc_add(float* acc, uint4 q) {
    __half2* h = (__half2*)&q;
#pragma unroll
    for (int k = 0; k < 4; k++) {
        float2 f = __half22float2(h[k]);
        acc[2 * k]     += f.x;
        acc[2 * k + 1] += f.y;
    }
}

template <bool FINAL>
__global__ void __launch_bounds__(ROWS_PER_BLK * LH)
k_hop(int parity, float* __restrict__ dout) {
    const uint4* __restrict__ uin = parity ? g_uB : g_uA;
    uint4* __restrict__ uout      = parity ? g_uA : g_uB;

    int tid  = threadIdx.x;
    int r    = blockIdx.x * ROWS_PER_BLK + tid / LH;
    int lane = tid % LH;
    if (r >= NN) return;

    int lo = g_rowptr[r];
    int hi = g_rowptr[r + 1];

    const uint4* base = uin + lane;
    float acc[8] = {0, 0, 0, 0, 0, 0, 0, 0};
    acc_add(acc, base[(size_t)r * LH]);   // self loop: + u[i]

    int e = lo;
    for (; e + 4 <= hi; e += 4) {
        int c0 = g_col[e], c1 = g_col[e + 1], c2 = g_col[e + 2], c3 = g_col[e + 3];
        uint4 q0 = base[(size_t)c0 * LH];
        uint4 q1 = base[(size_t)c1 * LH];
        uint4 q2 = base[(size_t)c2 * LH];
        uint4 q3 = base[(size_t)c3 * LH];
        acc_add(acc, q0); acc_add(acc, q1); acc_add(acc, q2); acc_add(acc, q3);
    }
    for (; e < hi; e++) {
        uint4 q = base[(size_t)g_col[e] * LH];
        acc_add(acc, q);
    }

    float di = g_dinv[r];
    float s  = 0.9f * di;
    uint4 v0q = g_v0h[(size_t)r * LH + lane];
    __half2* vh = (__half2*)&v0q;
    float o[8];
#pragma unroll
    for (int k = 0; k < 4; k++) {
        float2 f = __half22float2(vh[k]);
        o[2 * k]     = s * acc[2 * k]     + f.x;
        o[2 * k + 1] = s * acc[2 * k + 1] + f.y;
    }

    if (FINAL) {
        float4 a = make_float4(o[0], o[1], o[2], o[3]);
        float4 b = make_float4(o[4], o[5], o[6], o[7]);
        if (lane < 16) {
            // x region: feature base = lane*8, float4 idx = r*32 + lane*2
            float4* ox = (float4*)dout;
            ox[(size_t)r * 32 + lane * 2]     = a;
            ox[(size_t)r * 32 + lane * 2 + 1] = b;
        } else {
            // y region: feature base = (lane-16)*8
            float4* oy = (float4*)(dout + (size_t)NN * 128);
            int l = lane - 16;
            oy[(size_t)r * 16 + l * 2]     = a;
            oy[(size_t)r * 16 + l * 2 + 1] = b;
        }
    } else {
        uint4 wq;
        __half2* wh = (__half2*)&wq;
#pragma unroll
        for (int k = 0; k < 4; k++)
            wh[k] = __floats2half2_rn(di * o[2 * k], di * o[2 * k + 1]);
        uout[(size_t)r * LH + lane] = wq;
    }
}

// ---------------- launch ----------------

extern "C" void kernel_launch(void* const* d_in, const int* in_sizes, int n_in,
                              void* d_out, int out_size) {
    const float* x  = (const float*)d_in[0];
    const float* y  = (const float*)d_in[1];
    const int*   ei = (const int*)d_in[2];   // raw words; dtype detected on-device
    float* out = (float*)d_out;

    const int TB = 256;
    k_detect<<<1, 256>>>(ei);
    k_init<<<(NN + TB - 1) / TB, TB>>>();
    k_hist<<<(EE + TB - 1) / TB, TB>>>(ei);
    k_dinv<<<(NN + TB - 1) / TB, TB>>>();
    k_scan<<<1, 1024>>>();
    k_scatter<<<(EE + TB - 1) / TB, TB>>>(ei);
    k_pack<<<NN, DD>>>(x, y);

    const int hopThreads = ROWS_PER_BLK * LH;                       // 192
    const int hopBlocks  = (NN + ROWS_PER_BLK - 1) / ROWS_PER_BLK;  // 12500
    for (int h = 0; h < HOPS - 1; h++)
        k_hop<false><<<hopBlocks, hopThreads>>>(h & 1, out);
    k_hop<true><<<hopBlocks, hopThreads>>>((HOPS - 1) & 1, out);
}

// round 4
// speedup vs baseline: 1.7777x; 1.0848x over previous
#include <cuda_runtime.h>
#include <cuda_fp16.h>

#define NN 100000
#define EE 3200000
#define DD 192        // packed feature dim: 128 (x) + 64 (y)
#define LH 24         // uint4 lanes per row (192 halves / 8 per 16B)
#define ROWS_PER_BLK 8
#define HOPS 10

// ---- static scratch (no dynamic allocation allowed) ----
__device__ int    g_is64;          // 1 if edge_index is int64, 0 if int32
__device__ int    g_deg[NN];       // in-degree over dst (self loop added in dinv)
__device__ int    g_cnt[NN];       // out-degree over src (CSR row sizes)
__device__ int    g_fill[NN];
__device__ int    g_rowptr[NN + 1];
__device__ int    g_col[EE];
__device__ float  g_dinv[NN];
__device__ int    g_order[NN];     // rows sorted by degree (descending)
__device__ int    g_bcnt[256];
__device__ int    g_boff[256];
__device__ int    g_bfill[256];
__device__ uint4  g_v0h[NN * LH];  // 0.1 * v0, fp16 packed
__device__ uint4  g_uA[NN * LH];   // u = dinv .* v, fp16 (ping)
__device__ uint4  g_uB[NN * LH];   // (pong)

// ---------------- dtype detection ----------------
// int64 LE with values < 2^31: every odd 32-bit word is 0. int32: practically never.
__global__ void k_detect(const int* __restrict__ w) {
    __shared__ int nz;
    if (threadIdx.x == 0) nz = 0;
    __syncthreads();
    int local = 0;
    for (int i = threadIdx.x; i < 1024; i += blockDim.x)
        if (w[2 * i + 1] != 0) local++;
    if (local) atomicAdd(&nz, local);
    __syncthreads();
    if (threadIdx.x == 0) g_is64 = (nz == 0) ? 1 : 0;
}

__device__ __forceinline__ int edge_val(const int* __restrict__ w, long long idx) {
    return g_is64 ? w[2 * idx] : w[idx];
}

// ---------------- CSR build ----------------

__global__ void k_zero() {
    int i = blockIdx.x * blockDim.x + threadIdx.x;
    if (i < NN) { g_deg[i] = 0; g_cnt[i] = 0; g_fill[i] = 0; }
    if (i < 256) { g_bcnt[i] = 0; g_bfill[i] = 0; }
}

__global__ void k_hist(const int* __restrict__ w) {
    int e = blockIdx.x * blockDim.x + threadIdx.x;
    if (e < EE) {
        int s = edge_val(w, e);
        int d = edge_val(w, (long long)EE + e);
        if ((unsigned)s < NN && (unsigned)d < NN) {
            atomicAdd(&g_cnt[s], 1);
            atomicAdd(&g_deg[d], 1);
        }
    }
}

__global__ void k_dinv() {
    int i = blockIdx.x * blockDim.x + threadIdx.x;
    if (i < NN) g_dinv[i] = rsqrtf((float)(g_deg[i] + 1));   // +1 self loop
}

// single-block exclusive scan of g_cnt -> g_rowptr
__global__ void k_scan() {
    __shared__ int ssum[1024];
    const int T = 1024;
    int t = threadIdx.x;
    int per = (NN + T - 1) / T;
    int lo = t * per;
    int hi = lo + per; if (hi > NN) hi = NN;
    int s = 0;
    for (int i = lo; i < hi; i++) s += g_cnt[i];
    ssum[t] = s;
    __syncthreads();
    if (t == 0) {
        int acc = 0;
        for (int i = 0; i < T; i++) { int v = ssum[i]; ssum[i] = acc; acc += v; }
        g_rowptr[NN] = acc;
    }
    __syncthreads();
    int acc = ssum[t];
    for (int i = lo; i < hi; i++) { int v = g_cnt[i]; g_rowptr[i] = acc; acc += v; }
}

__global__ void k_scatter(const int* __restrict__ w) {
    int e = blockIdx.x * blockDim.x + threadIdx.x;
    if (e < EE) {
        int s = edge_val(w, e);
        int d = edge_val(w, (long long)EE + e);
        if ((unsigned)s < NN && (unsigned)d < NN) {
            int pos = g_rowptr[s] + atomicAdd(&g_fill[s], 1);
            g_col[pos] = d;
        }
    }
}

// ---------------- degree-ordered row permutation (counting sort, descending) ----------------

__global__ void k_bhist() {
    __shared__ int h[256];
    for (int i = threadIdx.x; i < 256; i += blockDim.x) h[i] = 0;
    __syncthreads();
    int i = blockIdx.x * blockDim.x + threadIdx.x;
    if (i < NN) { int d = g_cnt[i]; if (d > 255) d = 255; atomicAdd(&h[d], 1); }
    __syncthreads();
    for (int i = threadIdx.x; i < 256; i += blockDim.x)
        if (h[i]) atomicAdd(&g_bcnt[i], h[i]);
}

__global__ void k_bscan() {
    if (threadIdx.x == 0) {
        int acc = 0;
        for (int d = 255; d >= 0; d--) { g_boff[d] = acc; acc += g_bcnt[d]; }
    }
}

__global__ void k_border() {
    int i = blockIdx.x * blockDim.x + threadIdx.x;
    if (i < NN) {
        int d = g_cnt[i]; if (d > 255) d = 255;
        int pos = g_boff[d] + atomicAdd(&g_bfill[d], 1);
        g_order[pos] = i;
    }
}

// ---------------- pack (vectorized): v0h = fp16(0.1*v), uA = fp16(dinv*v) ----------------

__global__ void k_pack(const float* __restrict__ x, const float* __restrict__ y) {
    int t = blockIdx.x * blockDim.x + threadIdx.x;   // one thread per (row, 8-feature chunk)
    if (t >= NN * LH) return;
    int row = t / LH;
    int j   = t % LH;
    float di = g_dinv[row];

    float4 a, b;
    if (j < 16) {
        const float4* xr = (const float4*)(x + (size_t)row * 128 + j * 8);
        a = xr[0]; b = xr[1];
    } else {
        const float4* yr = (const float4*)(y + (size_t)row * 64 + (j - 16) * 8);
        a = yr[0]; b = yr[1];
    }

    uint4 qv, qu;
    __half2* hv = (__half2*)&qv;
    __half2* hu = (__half2*)&qu;
    hv[0] = __floats2half2_rn(0.1f * a.x, 0.1f * a.y);
    hv[1] = __floats2half2_rn(0.1f * a.z, 0.1f * a.w);
    hv[2] = __floats2half2_rn(0.1f * b.x, 0.1f * b.y);
    hv[3] = __floats2half2_rn(0.1f * b.z, 0.1f * b.w);
    hu[0] = __floats2half2_rn(di * a.x, di * a.y);
    hu[1] = __floats2half2_rn(di * a.z, di * a.w);
    hu[2] = __floats2half2_rn(di * b.x, di * b.y);
    hu[3] = __floats2half2_rn(di * b.z, di * b.w);
    g_v0h[t] = qv;
    g_uA[t]  = qu;
}

// ---------------- propagation hop ----------------
// (A_hat v)[i] = dinv[i] * ( u[i] + sum_{c in nbr(i)} u[c] ),  u = dinv .* v
// out = 0.9 * A_hat v + 0.1 * v0;  non-final stores fp16 u_out = dinv[i]*out

__device__ __forceinline__ void acc_add(float* acc, uint4 q) {
    __half2* h = (__half2*)&q;
#pragma unroll
    for (int k = 0; k < 4; k++) {
        float2 f = __half22float2(h[k]);
        acc[2 * k]     += f.x;
        acc[2 * k + 1] += f.y;
    }
}

template <bool FINAL>
__global__ void __launch_bounds__(ROWS_PER_BLK * LH)
k_hop(int parity, float* __restrict__ dout) {
    const uint4* __restrict__ uin = parity ? g_uB : g_uA;
    uint4* __restrict__ uout      = parity ? g_uA : g_uB;

    int tid  = threadIdx.x;
    int g    = blockIdx.x * ROWS_PER_BLK + tid / LH;
    int lane = tid % LH;
    if (g >= NN) return;
    int r = g_order[g];   // degree-sorted: warp-mates have near-equal degree

    int lo = g_rowptr[r];
    int hi = g_rowptr[r + 1];

    const uint4* base = uin + lane;
    float acc[8] = {0, 0, 0, 0, 0, 0, 0, 0};
    acc_add(acc, base[(size_t)r * LH]);   // self loop: + u[i]

    int e = lo;
    for (; e + 4 <= hi; e += 4) {
        int c0 = g_col[e], c1 = g_col[e + 1], c2 = g_col[e + 2], c3 = g_col[e + 3];
        uint4 q0 = base[(size_t)c0 * LH];
        uint4 q1 = base[(size_t)c1 * LH];
        uint4 q2 = base[(size_t)c2 * LH];
        uint4 q3 = base[(size_t)c3 * LH];
        acc_add(acc, q0); acc_add(acc, q1); acc_add(acc, q2); acc_add(acc, q3);
    }
    for (; e < hi; e++) {
        uint4 q = base[(size_t)g_col[e] * LH];
        acc_add(acc, q);
    }

    float di = g_dinv[r];
    float s  = 0.9f * di;
    uint4 v0q = g_v0h[(size_t)r * LH + lane];
    __half2* vh = (__half2*)&v0q;
    float o[8];
#pragma unroll
    for (int k = 0; k < 4; k++) {
        float2 f = __half22float2(vh[k]);
        o[2 * k]     = s * acc[2 * k]     + f.x;
        o[2 * k + 1] = s * acc[2 * k + 1] + f.y;
    }

    if (FINAL) {
        float4 a = make_float4(o[0], o[1], o[2], o[3]);
        float4 b = make_float4(o[4], o[5], o[6], o[7]);
        if (lane < 16) {
            float4* ox = (float4*)dout;                      // x region [N,128]
            ox[(size_t)r * 32 + lane * 2]     = a;
            ox[(size_t)r * 32 + lane * 2 + 1] = b;
        } else {
            float4* oy = (float4*)(dout + (size_t)NN * 128); // y region [N,64]
            int l = lane - 16;
            oy[(size_t)r * 16 + l * 2]     = a;
            oy[(size_t)r * 16 + l * 2 + 1] = b;
        }
    } else {
        uint4 wq;
        __half2* wh = (__half2*)&wq;
#pragma unroll
        for (int k = 0; k < 4; k++)
            wh[k] = __floats2half2_rn(di * o[2 * k], di * o[2 * k + 1]);
        uout[(size_t)r * LH + lane] = wq;
    }
}

// ---------------- launch ----------------

extern "C" void kernel_launch(void* const* d_in, const int* in_sizes, int n_in,
                              void* d_out, int out_size) {
    const float* x  = (const float*)d_in[0];
    const float* y  = (const float*)d_in[1];
    const int*   ei = (const int*)d_in[2];   // raw words; dtype detected on-device
    float* out = (float*)d_out;

    const int TB = 256;
    k_detect<<<1, 256>>>(ei);
    k_zero<<<(NN + TB - 1) / TB, TB>>>();
    k_hist<<<(EE + TB - 1) / TB, TB>>>(ei);
    k_dinv<<<(NN + TB - 1) / TB, TB>>>();
    k_scan<<<1, 1024>>>();
    k_scatter<<<(EE + TB - 1) / TB, TB>>>(ei);
    k_bhist<<<(NN + TB - 1) / TB, TB>>>();
    k_bscan<<<1, 32>>>();
    k_border<<<(NN + TB - 1) / TB, TB>>>();
    k_pack<<<(NN * LH + TB - 1) / TB, TB>>>(x, y);

    const int hopThreads = ROWS_PER_BLK * LH;                       // 192
    const int hopBlocks  = (NN + ROWS_PER_BLK - 1) / ROWS_PER_BLK;  // 12500
    for (int h = 0; h < HOPS - 1; h++)
        k_hop<false><<<hopBlocks, hopThreads>>>(h & 1, out);
    k_hop<true><<<hopBlocks, hopThreads>>>((HOPS - 1) & 1, out);
}